// round 2
// baseline (speedup 1.0000x reference)
#include <cuda_runtime.h>
#include <cuda_bf16.h>
#include <cstdint>
#include <cmath>

// Problem constants
#define BB 4
#define SS 2048
#define DD 1024
#define HH 16
#define HD 64
#define MM (BB*SS)        // 8192
#define DFF (4*DD)        // 4096

// ---------------- device scratch (allocation-free rule: __device__ globals) --------
__device__ float g_h  [ (size_t)MM*DD ];      // LN1 out
__device__ float g_q  [ (size_t)MM*DD ];      // [B,H,S,HD]
__device__ float g_k  [ (size_t)MM*DD ];
__device__ float g_v  [ (size_t)MM*DD ];
__device__ float g_o  [ (size_t)MM*DD ];      // attn out, [B,S,D] (heads concatenated)
__device__ float g_x1 [ (size_t)MM*DD ];      // x + attn
__device__ float g_h2 [ (size_t)MM*DD ];      // LN2 out
__device__ float g_t  [ (size_t)MM*DFF ];     // FFN mid

// ---------------- LayerNorm: one block per row of 1024 ----------------------------
__global__ __launch_bounds__(256) void ln_kernel(const float* __restrict__ x,
                                                 const float* __restrict__ g,
                                                 const float* __restrict__ b,
                                                 float* __restrict__ y) {
    int row = blockIdx.x;
    int t   = threadIdx.x;             // 256 threads, 4 elems each
    const float* xr = x + (size_t)row * DD;
    float4 xv = *(const float4*)&xr[t * 4];
    float s  = xv.x + xv.y + xv.z + xv.w;
    float s2 = xv.x*xv.x + xv.y*xv.y + xv.z*xv.z + xv.w*xv.w;
    #pragma unroll
    for (int mk = 16; mk >= 1; mk >>= 1) {
        s  += __shfl_xor_sync(0xffffffffu, s,  mk);
        s2 += __shfl_xor_sync(0xffffffffu, s2, mk);
    }
    __shared__ float red[16];
    int w = t >> 5;
    if ((t & 31) == 0) { red[w] = s; red[8 + w] = s2; }
    __syncthreads();
    float ts = 0.f, ts2 = 0.f;
    #pragma unroll
    for (int i = 0; i < 8; i++) { ts += red[i]; ts2 += red[8 + i]; }
    float mu  = ts  * (1.0f / DD);
    float var = ts2 * (1.0f / DD) - mu * mu;
    float rs  = rsqrtf(var + 1e-5f);
    float4 gv = *(const float4*)&g[t * 4];
    float4 bv = *(const float4*)&b[t * 4];
    float4 yv;
    yv.x = (xv.x - mu) * rs * gv.x + bv.x;
    yv.y = (xv.y - mu) * rs * gv.y + bv.y;
    yv.z = (xv.z - mu) * rs * gv.z + bv.z;
    yv.w = (xv.w - mu) * rs * gv.w + bv.w;
    *(float4*)&y[(size_t)row * DD + t * 4] = yv;
}

// ---------------- Tiled fp32 GEMM, 64x64x16, 256 thr, 4x4 microtile ---------------
// MODE 0: QKV  — Bw is [H,D,HD] gathered; bias[n]; scatter C to [B,H,S,HD]
// MODE 1: WO   — plain Bw [D,D]; bias; C = resid + acc    (resid = x)
// MODE 2: FF1  — plain Bw [D,4D]; bias; C = acc
// MODE 3: FF2  — plain Bw [4D,D]; bias; C = resid + gelu(acc+bias)  (resid = x1)
template<int MODE>
__global__ __launch_bounds__(256) void gemm64(const float* __restrict__ A,
                                              const float* __restrict__ Bw,
                                              const float* __restrict__ bias,
                                              const float* __restrict__ resid,
                                              float* __restrict__ C,
                                              int K, int N) {
    __shared__ float As[16][68];   // [k][m], padded
    __shared__ float Bs[16][64];   // [k][n]

    int t  = threadIdx.x;
    int tx = t & 15, ty = t >> 4;
    int m0 = blockIdx.y * 64, n0 = blockIdx.x * 64;

    int la_r = t >> 2;            // 0..63  (m within tile)
    int la_k = (t & 3) * 4;       // 0,4,8,12
    int lb_k = t >> 4;            // 0..15
    int lb_n = (t & 15) * 4;      // 0..60

    float acc[4][4];
    #pragma unroll
    for (int i = 0; i < 4; i++)
        #pragma unroll
        for (int j = 0; j < 4; j++) acc[i][j] = 0.f;

    for (int k0 = 0; k0 < K; k0 += 16) {
        float4 av = *(const float4*)&A[(size_t)(m0 + la_r) * K + k0 + la_k];
        float4 bv;
        if (MODE == 0) {
            int head = n0 >> 6;  // BN=64 tiles align with heads
            bv = *(const float4*)&Bw[((size_t)head * K + (k0 + lb_k)) * 64 + lb_n];
        } else {
            bv = *(const float4*)&Bw[(size_t)(k0 + lb_k) * N + n0 + lb_n];
        }
        As[la_k + 0][la_r] = av.x;
        As[la_k + 1][la_r] = av.y;
        As[la_k + 2][la_r] = av.z;
        As[la_k + 3][la_r] = av.w;
        *(float4*)&Bs[lb_k][lb_n] = bv;
        __syncthreads();

        #pragma unroll
        for (int kk = 0; kk < 16; kk++) {
            float4 a4 = *(const float4*)&As[kk][ty * 4];
            float4 b4 = *(const float4*)&Bs[kk][tx * 4];
            acc[0][0] += a4.x * b4.x; acc[0][1] += a4.x * b4.y;
            acc[0][2] += a4.x * b4.z; acc[0][3] += a4.x * b4.w;
            acc[1][0] += a4.y * b4.x; acc[1][1] += a4.y * b4.y;
            acc[1][2] += a4.y * b4.z; acc[1][3] += a4.y * b4.w;
            acc[2][0] += a4.z * b4.x; acc[2][1] += a4.z * b4.y;
            acc[2][2] += a4.z * b4.z; acc[2][3] += a4.z * b4.w;
            acc[3][0] += a4.w * b4.x; acc[3][1] += a4.w * b4.y;
            acc[3][2] += a4.w * b4.z; acc[3][3] += a4.w * b4.w;
        }
        __syncthreads();
    }

    #pragma unroll
    for (int i = 0; i < 4; i++) {
        int m  = m0 + ty * 4 + i;
        int b_ = m >> 11;           // /2048
        int s_ = m & 2047;
        #pragma unroll
        for (int j = 0; j < 4; j++) {
            int n = n0 + tx * 4 + j;
            float vacc = acc[i][j] + bias[n];
            if (MODE == 0) {
                int head = n >> 6, c = n & 63;
                C[(((size_t)b_ * HH + head) * SS + s_) * HD + c] = vacc;
            } else if (MODE == 1) {
                size_t idx = (size_t)m * N + n;
                C[idx] = vacc + resid[idx];
            } else if (MODE == 2) {
                C[(size_t)m * N + n] = vacc;
            } else {
                size_t idx = (size_t)m * DD + n;
                float gel = 0.5f * vacc * (1.0f + erff(vacc * 0.70710678118654752f));
                C[idx] = resid[idx] + gel;
            }
        }
    }
}

// ---------------- Flash attention fp32: 64-query x 64-key tiles, HD=64 ------------
// grid: (S/64, B*H), 256 threads. Online softmax. 66.5 KB dynamic smem.
__global__ __launch_bounds__(256) void attn_kernel(const float* __restrict__ q,
                                                   const float* __restrict__ k,
                                                   const float* __restrict__ v,
                                                   float* __restrict__ o) {
    extern __shared__ float sm[];
    float* qT = sm;                // [d][r]   64x64
    float* kT = sm + 4096;         // [d][c]   64x64
    float* vs = sm + 8192;         // [key][j] 64x64
    float* pT = sm + 12288;        // [key][r] 64x68 (padded)

    int bh = blockIdx.y;
    int qt = blockIdx.x;
    const float* qb = q + (size_t)bh * SS * HD;
    const float* kb = k + (size_t)bh * SS * HD;
    const float* vb = v + (size_t)bh * SS * HD;

    int t  = threadIdx.x;
    int tx = t & 15, ty = t >> 4;
    int lr = t >> 2;              // row 0..63
    int ld = (t & 3) * 4;         // dim offset 0,4,8,12

    // load Q tile transposed, pre-scaled by 1/sqrt(HD)=0.125
    #pragma unroll
    for (int du = 0; du < 64; du += 16) {
        float4 qv = *(const float4*)&qb[(size_t)(qt * 64 + lr) * HD + du + ld];
        qT[(du + ld + 0) * 64 + lr] = qv.x * 0.125f;
        qT[(du + ld + 1) * 64 + lr] = qv.y * 0.125f;
        qT[(du + ld + 2) * 64 + lr] = qv.z * 0.125f;
        qT[(du + ld + 3) * 64 + lr] = qv.w * 0.125f;
    }

    float m_r[4], l_r[4], oa[4][4];
    #pragma unroll
    for (int i = 0; i < 4; i++) {
        m_r[i] = -1e30f; l_r[i] = 0.f;
        #pragma unroll
        for (int j = 0; j < 4; j++) oa[i][j] = 0.f;
    }

    for (int kt = 0; kt < SS / 64; kt++) {
        __syncthreads();   // protect kT/vs/pT (and qT on first iter)
        const float* kbt = kb + (size_t)kt * 64 * HD;
        const float* vbt = vb + (size_t)kt * 64 * HD;
        #pragma unroll
        for (int du = 0; du < 64; du += 16) {
            float4 kv = *(const float4*)&kbt[(size_t)lr * HD + du + ld];
            kT[(du + ld + 0) * 64 + lr] = kv.x;
            kT[(du + ld + 1) * 64 + lr] = kv.y;
            kT[(du + ld + 2) * 64 + lr] = kv.z;
            kT[(du + ld + 3) * 64 + lr] = kv.w;
            float4 vv = *(const float4*)&vbt[(size_t)lr * HD + du + ld];
            *(float4*)&vs[lr * 64 + du + ld] = vv;
        }
        __syncthreads();

        // scores S = (Q/8) K^T : 4x4 microtile
        float sc[4][4];
        #pragma unroll
        for (int i = 0; i < 4; i++)
            #pragma unroll
            for (int j = 0; j < 4; j++) sc[i][j] = 0.f;
        #pragma unroll 8
        for (int d = 0; d < 64; d++) {
            float4 a4 = *(const float4*)&qT[d * 64 + ty * 4];
            float4 b4 = *(const float4*)&kT[d * 64 + tx * 4];
            sc[0][0] += a4.x * b4.x; sc[0][1] += a4.x * b4.y;
            sc[0][2] += a4.x * b4.z; sc[0][3] += a4.x * b4.w;
            sc[1][0] += a4.y * b4.x; sc[1][1] += a4.y * b4.y;
            sc[1][2] += a4.y * b4.z; sc[1][3] += a4.y * b4.w;
            sc[2][0] += a4.z * b4.x; sc[2][1] += a4.z * b4.y;
            sc[2][2] += a4.z * b4.z; sc[2][3] += a4.z * b4.w;
            sc[3][0] += a4.w * b4.x; sc[3][1] += a4.w * b4.y;
            sc[3][2] += a4.w * b4.z; sc[3][3] += a4.w * b4.w;
        }

        // online softmax (row owned by 16 lanes with same ty; xor-reduce width 16)
        #pragma unroll
        for (int i = 0; i < 4; i++) {
            float rm = fmaxf(fmaxf(sc[i][0], sc[i][1]), fmaxf(sc[i][2], sc[i][3]));
            rm = fmaxf(rm, __shfl_xor_sync(0xffffffffu, rm, 1));
            rm = fmaxf(rm, __shfl_xor_sync(0xffffffffu, rm, 2));
            rm = fmaxf(rm, __shfl_xor_sync(0xffffffffu, rm, 4));
            rm = fmaxf(rm, __shfl_xor_sync(0xffffffffu, rm, 8));
            float mn   = fmaxf(m_r[i], rm);
            float corr = __expf(m_r[i] - mn);
            float ps = 0.f;
            #pragma unroll
            for (int j = 0; j < 4; j++) {
                float p = __expf(sc[i][j] - mn);
                sc[i][j] = p; ps += p;
            }
            ps += __shfl_xor_sync(0xffffffffu, ps, 1);
            ps += __shfl_xor_sync(0xffffffffu, ps, 2);
            ps += __shfl_xor_sync(0xffffffffu, ps, 4);
            ps += __shfl_xor_sync(0xffffffffu, ps, 8);
            l_r[i] = l_r[i] * corr + ps;
            m_r[i] = mn;
            #pragma unroll
            for (int j = 0; j < 4; j++) oa[i][j] *= corr;
        }

        // store P transposed (pT[key][row]) then O += P * V
        #pragma unroll
        for (int j = 0; j < 4; j++) {
            float4 pv = make_float4(sc[0][j], sc[1][j], sc[2][j], sc[3][j]);
            *(float4*)&pT[(tx * 4 + j) * 68 + ty * 4] = pv;
        }
        __syncthreads();
        #pragma unroll 8
        for (int key = 0; key < 64; key++) {
            float4 a4 = *(const float4*)&pT[key * 68 + ty * 4];
            float4 b4 = *(const float4*)&vs[key * 64 + tx * 4];
            oa[0][0] += a4.x * b4.x; oa[0][1] += a4.x * b4.y;
            oa[0][2] += a4.x * b4.z; oa[0][3] += a4.x * b4.w;
            oa[1][0] += a4.y * b4.x; oa[1][1] += a4.y * b4.y;
            oa[1][2] += a4.y * b4.z; oa[1][3] += a4.y * b4.w;
            oa[2][0] += a4.z * b4.x; oa[2][1] += a4.z * b4.y;
            oa[2][2] += a4.z * b4.z; oa[2][3] += a4.z * b4.w;
            oa[3][0] += a4.w * b4.x; oa[3][1] += a4.w * b4.y;
            oa[3][2] += a4.w * b4.z; oa[3][3] += a4.w * b4.w;
        }
    }

    // write O in [B,S,D] layout (heads concatenated)
    int b_ = bh >> 4, h_ = bh & 15;
    #pragma unroll
    for (int i = 0; i < 4; i++) {
        int srow = qt * 64 + ty * 4 + i;
        float inv = 1.0f / l_r[i];
        #pragma unroll
        for (int j = 0; j < 4; j++) {
            o[((size_t)b_ * SS + srow) * DD + h_ * HD + tx * 4 + j] = oa[i][j] * inv;
        }
    }
}

// ---------------- host launch ------------------------------------------------------
extern "C" void kernel_launch(void* const* d_in, const int* in_sizes, int n_in,
                              void* d_out, int out_size) {
    const float* x   = (const float*)d_in[0];
    const float* Wq  = (const float*)d_in[1];
    const float* bq  = (const float*)d_in[2];
    const float* Wk  = (const float*)d_in[3];
    const float* bk  = (const float*)d_in[4];
    const float* Wv  = (const float*)d_in[5];
    const float* bv  = (const float*)d_in[6];
    const float* Wo  = (const float*)d_in[7];
    const float* bo  = (const float*)d_in[8];
    const float* W1  = (const float*)d_in[9];
    const float* b1  = (const float*)d_in[10];
    const float* W2  = (const float*)d_in[11];
    const float* b2  = (const float*)d_in[12];
    const float* g1  = (const float*)d_in[13];
    const float* be1 = (const float*)d_in[14];
    const float* g2  = (const float*)d_in[15];
    const float* be2 = (const float*)d_in[16];
    float* out = (float*)d_out;

    float *h, *qb, *kb, *vb, *ob, *x1, *h2, *tmid;
    cudaGetSymbolAddress((void**)&h,    g_h);
    cudaGetSymbolAddress((void**)&qb,   g_q);
    cudaGetSymbolAddress((void**)&kb,   g_k);
    cudaGetSymbolAddress((void**)&vb,   g_v);
    cudaGetSymbolAddress((void**)&ob,   g_o);
    cudaGetSymbolAddress((void**)&x1,   g_x1);
    cudaGetSymbolAddress((void**)&h2,   g_h2);
    cudaGetSymbolAddress((void**)&tmid, g_t);

    cudaFuncSetAttribute(attn_kernel, cudaFuncAttributeMaxDynamicSharedMemorySize, 68 * 1024);

    dim3 gSq(DD / 64,  MM / 64);   // N=1024 tiles x M tiles
    dim3 gFF(DFF / 64, MM / 64);   // N=4096 tiles

    ln_kernel<<<MM, 256>>>(x, g1, be1, h);

    gemm64<0><<<gSq, 256>>>(h, Wq, bq, nullptr, qb, DD, DD);
    gemm64<0><<<gSq, 256>>>(h, Wk, bk, nullptr, kb, DD, DD);
    gemm64<0><<<gSq, 256>>>(h, Wv, bv, nullptr, vb, DD, DD);

    attn_kernel<<<dim3(SS / 64, BB * HH), 256, 66560>>>(qb, kb, vb, ob);

    gemm64<1><<<gSq, 256>>>(ob, Wo, bo, x, x1, DD, DD);

    ln_kernel<<<MM, 256>>>(x1, g2, be2, h2);

    gemm64<2><<<gFF, 256>>>(h2, W1, b1, nullptr, tmid, DD, DFF);
    gemm64<3><<<gSq, 256>>>(tmid, W2, b2, x1, out, DFF, DD);
}

// round 3
// speedup vs baseline: 3.4610x; 3.4610x over previous
#include <cuda_runtime.h>
#include <cuda_bf16.h>
#include <cstdint>
#include <cmath>

#define BB 4
#define SS 2048
#define DD 1024
#define HH 16
#define HD 64
#define MM (BB*SS)        // 8192
#define DFF (4*DD)        // 4096

// ---------------- device scratch ---------------------------------------------------
__device__ float g_h  [ (size_t)MM*DD ];      // LN1 out
__device__ float g_q  [ (size_t)MM*DD ];      // [B,H,S,HD]
__device__ float g_k  [ (size_t)MM*DD ];
__device__ float g_v  [ (size_t)MM*DD ];
__device__ float g_o  [ (size_t)MM*DD ];      // attn out [B,S,D]
__device__ float g_x1 [ (size_t)MM*DD ];      // x + attn
__device__ float g_h2 [ (size_t)MM*DD ];      // LN2 out
__device__ float g_t  [ (size_t)MM*DFF ];     // FFN mid

// ---------------- helpers ----------------------------------------------------------
__device__ __forceinline__ void cp16(uint32_t s, const void* g) {
    asm volatile("cp.async.cg.shared.global [%0], [%1], 16;" :: "r"(s), "l"(g));
}
__device__ __forceinline__ uint32_t fbits(float f) { return __float_as_uint(f); }

#define MMA_TF32(c, a0,a1,a2,a3, b0,b1) \
  asm volatile("mma.sync.aligned.m16n8k8.row.col.f32.tf32.tf32.f32 " \
    "{%0,%1,%2,%3}, {%4,%5,%6,%7}, {%8,%9}, {%0,%1,%2,%3};" \
    : "+f"(c[0]), "+f"(c[1]), "+f"(c[2]), "+f"(c[3]) \
    : "r"(a0), "r"(a1), "r"(a2), "r"(a3), "r"(b0), "r"(b1))

// ---------------- LayerNorm --------------------------------------------------------
__global__ __launch_bounds__(256) void ln_kernel(const float* __restrict__ x,
                                                 const float* __restrict__ g,
                                                 const float* __restrict__ b,
                                                 float* __restrict__ y) {
    int row = blockIdx.x;
    int t   = threadIdx.x;
    const float* xr = x + (size_t)row * DD;
    float4 xv = *(const float4*)&xr[t * 4];
    float s  = xv.x + xv.y + xv.z + xv.w;
    float s2 = xv.x*xv.x + xv.y*xv.y + xv.z*xv.z + xv.w*xv.w;
    #pragma unroll
    for (int mk = 16; mk >= 1; mk >>= 1) {
        s  += __shfl_xor_sync(0xffffffffu, s,  mk);
        s2 += __shfl_xor_sync(0xffffffffu, s2, mk);
    }
    __shared__ float red[16];
    int w = t >> 5;
    if ((t & 31) == 0) { red[w] = s; red[8 + w] = s2; }
    __syncthreads();
    float ts = 0.f, ts2 = 0.f;
    #pragma unroll
    for (int i = 0; i < 8; i++) { ts += red[i]; ts2 += red[8 + i]; }
    float mu  = ts  * (1.0f / DD);
    float var = ts2 * (1.0f / DD) - mu * mu;
    float rs  = rsqrtf(var + 1e-5f);
    float4 gv = *(const float4*)&g[t * 4];
    float4 bv = *(const float4*)&b[t * 4];
    float4 yv;
    yv.x = (xv.x - mu) * rs * gv.x + bv.x;
    yv.y = (xv.y - mu) * rs * gv.y + bv.y;
    yv.z = (xv.z - mu) * rs * gv.z + bv.z;
    yv.w = (xv.w - mu) * rs * gv.w + bv.w;
    *(float4*)&y[(size_t)row * DD + t * 4] = yv;
}

// ---------------- tf32 tensor-core GEMM, 128x128x32 CTA tile -----------------------
// MODE 0: QKV  — Bw [H,D,64] gathered; C scattered to [B,H,S,HD]
// MODE 1: WO   — C = acc + bias + resid
// MODE 2: FF1  — C = acc + bias
// MODE 3: FF2  — C = resid + gelu(acc + bias)
#define AS_STR 36
#define BS_STR 136
#define AS_FLOATS (128*AS_STR)   // 4608
#define BS_FLOATS (32*BS_STR)    // 4352
#define GEMM_SMEM ((AS_FLOATS + BS_FLOATS) * 2 * 4)   // 71680 bytes

template<int MODE>
__global__ __launch_bounds__(256, 2) void gemm_tc(const float* __restrict__ A,
                                                  const float* __restrict__ Bw,
                                                  const float* __restrict__ bias,
                                                  const float* __restrict__ resid,
                                                  float* __restrict__ C,
                                                  int K, int N) {
    extern __shared__ float sm[];
    float* Asb[2] = { sm,            sm + AS_FLOATS };
    float* Bsb[2] = { sm + 2*AS_FLOATS, sm + 2*AS_FLOATS + BS_FLOATS };

    int t  = threadIdx.x;
    int w  = t >> 5, l = t & 31;
    int wm = w >> 2, wn = w & 3;           // 2 x 4 warps
    int tg = l & 3,  gr = l >> 2;
    int m0 = blockIdx.y * 128, n0 = blockIdx.x * 128;

    float c[4][4][4];
    #pragma unroll
    for (int mi = 0; mi < 4; mi++)
        #pragma unroll
        for (int ni = 0; ni < 4; ni++)
            #pragma unroll
            for (int r = 0; r < 4; r++) c[mi][ni][r] = 0.f;

    auto load_tiles = [&](int k0, int buf) {
        #pragma unroll
        for (int j = 0; j < 4; j++) {
            int cc = t + j * 256;
            int row = cc >> 3, kc = (cc & 7) * 4;
            uint32_t sa = (uint32_t)__cvta_generic_to_shared(&Asb[buf][row*AS_STR + kc]);
            cp16(sa, &A[(size_t)(m0 + row) * K + k0 + kc]);
        }
        #pragma unroll
        for (int j = 0; j < 4; j++) {
            int cc = t + j * 256;
            int kr = cc >> 5, nc = (cc & 31) * 4;
            const float* gp;
            if (MODE == 0) {
                int n = n0 + nc; int head = n >> 6; int cw = n & 63;
                gp = &Bw[((size_t)head * K + (k0 + kr)) * 64 + cw];
            } else {
                gp = &Bw[(size_t)(k0 + kr) * N + n0 + nc];
            }
            uint32_t sa = (uint32_t)__cvta_generic_to_shared(&Bsb[buf][kr*BS_STR + nc]);
            cp16(sa, gp);
        }
        asm volatile("cp.async.commit_group;");
    };

    int nkt = K >> 5;
    load_tiles(0, 0);

    for (int kt = 0; kt < nkt; kt++) {
        int buf = kt & 1;
        if (kt + 1 < nkt) {
            load_tiles((kt + 1) << 5, buf ^ 1);
            asm volatile("cp.async.wait_group 1;");
        } else {
            asm volatile("cp.async.wait_group 0;");
        }
        __syncthreads();

        const float* As_ = Asb[buf];
        const float* Bs_ = Bsb[buf];
        #pragma unroll
        for (int ks = 0; ks < 4; ks++) {
            int kb = ks * 8;
            uint32_t a[4][4], b[4][2];
            #pragma unroll
            for (int mi = 0; mi < 4; mi++) {
                int rb = wm*64 + mi*16 + gr;
                a[mi][0] = fbits(As_[rb      *AS_STR + kb + tg    ]);
                a[mi][1] = fbits(As_[(rb + 8)*AS_STR + kb + tg    ]);
                a[mi][2] = fbits(As_[rb      *AS_STR + kb + tg + 4]);
                a[mi][3] = fbits(As_[(rb + 8)*AS_STR + kb + tg + 4]);
            }
            #pragma unroll
            for (int ni = 0; ni < 4; ni++) {
                int nb = wn*32 + ni*8 + gr;
                b[ni][0] = fbits(Bs_[(kb + tg    )*BS_STR + nb]);
                b[ni][1] = fbits(Bs_[(kb + tg + 4)*BS_STR + nb]);
            }
            #pragma unroll
            for (int mi = 0; mi < 4; mi++)
                #pragma unroll
                for (int ni = 0; ni < 4; ni++)
                    MMA_TF32(c[mi][ni], a[mi][0], a[mi][1], a[mi][2], a[mi][3],
                             b[ni][0], b[ni][1]);
        }
        __syncthreads();
    }

    // epilogue
    #pragma unroll
    for (int mi = 0; mi < 4; mi++) {
        int r = m0 + wm*64 + mi*16 + gr;
        #pragma unroll
        for (int ni = 0; ni < 4; ni++) {
            int cc = n0 + wn*32 + ni*8 + tg*2;
            float b0 = bias[cc], b1 = bias[cc + 1];
            float v0 = c[mi][ni][0] + b0;
            float v1 = c[mi][ni][1] + b1;
            float v2 = c[mi][ni][2] + b0;
            float v3 = c[mi][ni][3] + b1;
            if (MODE == 0) {
                int head = cc >> 6, cw = cc & 63;
                int b_ = r >> 11, s_ = r & 2047;
                size_t base0 = (((size_t)b_*HH + head)*SS + s_)*HD + cw;
                size_t base1 = (((size_t)b_*HH + head)*SS + (s_+8))*HD + cw;
                *(float2*)&C[base0] = make_float2(v0, v1);
                *(float2*)&C[base1] = make_float2(v2, v3);
            } else if (MODE == 1) {
                size_t i0 = (size_t)r*N + cc, i1 = (size_t)(r+8)*N + cc;
                float2 r0 = *(const float2*)&resid[i0];
                float2 r1 = *(const float2*)&resid[i1];
                *(float2*)&C[i0] = make_float2(v0 + r0.x, v1 + r0.y);
                *(float2*)&C[i1] = make_float2(v2 + r1.x, v3 + r1.y);
            } else if (MODE == 2) {
                *(float2*)&C[(size_t)r*N + cc]     = make_float2(v0, v1);
                *(float2*)&C[(size_t)(r+8)*N + cc] = make_float2(v2, v3);
            } else {
                size_t i0 = (size_t)r*DD + cc, i1 = (size_t)(r+8)*DD + cc;
                float2 r0 = *(const float2*)&resid[i0];
                float2 r1 = *(const float2*)&resid[i1];
                const float is2 = 0.70710678118654752f;
                float g0 = 0.5f*v0*(1.f + erff(v0*is2));
                float g1 = 0.5f*v1*(1.f + erff(v1*is2));
                float g2 = 0.5f*v2*(1.f + erff(v2*is2));
                float g3 = 0.5f*v3*(1.f + erff(v3*is2));
                *(float2*)&C[i0] = make_float2(r0.x + g0, r0.y + g1);
                *(float2*)&C[i1] = make_float2(r1.x + g2, r1.y + g3);
            }
        }
    }
}

// ---------------- tf32 tensor-core flash attention ---------------------------------
// 128-query tile, 64-key tiles, 8 warps (warp w owns q rows w*16..w*16+15)
#define QS_STR 68
#define KS_STR 68
#define VS_STR 72
#define PS_STR 68
#define ATTN_SMEM ((128*QS_STR + 64*KS_STR + 64*VS_STR + 128*PS_STR) * 4)  // 105472

__global__ __launch_bounds__(256, 2) void attn_tc(const float* __restrict__ q,
                                                  const float* __restrict__ k,
                                                  const float* __restrict__ v,
                                                  float* __restrict__ o) {
    extern __shared__ float sm[];
    float* Qs = sm;                       // [128][68]  (q rows x d)
    float* Ks = Qs + 128*QS_STR;          // [64][68]   (key rows x d)
    float* Vs = Ks + 64*KS_STR;           // [64][72]   (key rows x d)
    float* Ps = Vs + 64*VS_STR;           // [128][68]  (q rows x key)

    int t = threadIdx.x, w = t >> 5, l = t & 31;
    int tg = l & 3, gr = l >> 2;
    int bh = blockIdx.y, qt = blockIdx.x;
    const float* qb = q + (size_t)bh * SS * HD;
    const float* kb = k + (size_t)bh * SS * HD;
    const float* vb = v + (size_t)bh * SS * HD;

    // load Q tile scaled by 1/8
    #pragma unroll
    for (int j = 0; j < 8; j++) {
        int cc = t + j * 256;
        int row = cc >> 4, d4 = (cc & 15) * 4;
        float4 qv = *(const float4*)&qb[(size_t)(qt*128 + row)*HD + d4];
        qv.x *= 0.125f; qv.y *= 0.125f; qv.z *= 0.125f; qv.w *= 0.125f;
        *(float4*)&Qs[row*QS_STR + d4] = qv;
    }

    float mrow[2] = { -1e30f, -1e30f };
    float lrow[2] = { 0.f, 0.f };
    float oacc[8][4];
    #pragma unroll
    for (int ni = 0; ni < 8; ni++)
        #pragma unroll
        for (int r = 0; r < 4; r++) oacc[ni][r] = 0.f;

    int rb = w*16 + gr;     // in-tile q row (first half)

    for (int kt = 0; kt < SS/64; kt++) {
        // load K,V tiles (direct row-major copies)
        const float* kbt = kb + (size_t)kt * 64 * HD;
        const float* vbt = vb + (size_t)kt * 64 * HD;
        #pragma unroll
        for (int j = 0; j < 4; j++) {
            int cc = t + j * 256;
            int key = cc >> 4, d4 = (cc & 15) * 4;
            *(float4*)&Ks[key*KS_STR + d4] = *(const float4*)&kbt[(size_t)key*HD + d4];
            *(float4*)&Vs[key*VS_STR + d4] = *(const float4*)&vbt[(size_t)key*HD + d4];
        }
        __syncthreads();

        // S = Q K^T  (per-warp 16x64)
        float s[8][4];
        #pragma unroll
        for (int ni = 0; ni < 8; ni++)
            #pragma unroll
            for (int r = 0; r < 4; r++) s[ni][r] = 0.f;
        #pragma unroll
        for (int ks = 0; ks < 8; ks++) {
            int kb8 = ks * 8;
            uint32_t a0 = fbits(Qs[rb    *QS_STR + kb8 + tg    ]);
            uint32_t a1 = fbits(Qs[(rb+8)*QS_STR + kb8 + tg    ]);
            uint32_t a2 = fbits(Qs[rb    *QS_STR + kb8 + tg + 4]);
            uint32_t a3 = fbits(Qs[(rb+8)*QS_STR + kb8 + tg + 4]);
            #pragma unroll
            for (int ni = 0; ni < 8; ni++) {
                uint32_t b0 = fbits(Ks[(ni*8 + gr)*KS_STR + kb8 + tg    ]);
                uint32_t b1 = fbits(Ks[(ni*8 + gr)*KS_STR + kb8 + tg + 4]);
                MMA_TF32(s[ni], a0, a1, a2, a3, b0, b1);
            }
        }

        // online softmax: rows rb (s[ni][0..1]) and rb+8 (s[ni][2..3])
        float mx0 = -1e30f, mx1 = -1e30f;
        #pragma unroll
        for (int ni = 0; ni < 8; ni++) {
            mx0 = fmaxf(mx0, fmaxf(s[ni][0], s[ni][1]));
            mx1 = fmaxf(mx1, fmaxf(s[ni][2], s[ni][3]));
        }
        mx0 = fmaxf(mx0, __shfl_xor_sync(0xffffffffu, mx0, 1));
        mx0 = fmaxf(mx0, __shfl_xor_sync(0xffffffffu, mx0, 2));
        mx1 = fmaxf(mx1, __shfl_xor_sync(0xffffffffu, mx1, 1));
        mx1 = fmaxf(mx1, __shfl_xor_sync(0xffffffffu, mx1, 2));
        float mn0 = fmaxf(mrow[0], mx0), mn1 = fmaxf(mrow[1], mx1);
        float cor0 = __expf(mrow[0] - mn0), cor1 = __expf(mrow[1] - mn1);
        float ps0 = 0.f, ps1 = 0.f;
        #pragma unroll
        for (int ni = 0; ni < 8; ni++) {
            s[ni][0] = __expf(s[ni][0] - mn0); ps0 += s[ni][0];
            s[ni][1] = __expf(s[ni][1] - mn0); ps0 += s[ni][1];
            s[ni][2] = __expf(s[ni][2] - mn1); ps1 += s[ni][2];
            s[ni][3] = __expf(s[ni][3] - mn1); ps1 += s[ni][3];
        }
        ps0 += __shfl_xor_sync(0xffffffffu, ps0, 1);
        ps0 += __shfl_xor_sync(0xffffffffu, ps0, 2);
        ps1 += __shfl_xor_sync(0xffffffffu, ps1, 1);
        ps1 += __shfl_xor_sync(0xffffffffu, ps1, 2);
        lrow[0] = lrow[0]*cor0 + ps0;  mrow[0] = mn0;
        lrow[1] = lrow[1]*cor1 + ps1;  mrow[1] = mn1;
        #pragma unroll
        for (int ni = 0; ni < 8; ni++) {
            oacc[ni][0] *= cor0; oacc[ni][1] *= cor0;
            oacc[ni][2] *= cor1; oacc[ni][3] *= cor1;
        }

        // write P (per-warp rows) to smem
        #pragma unroll
        for (int ni = 0; ni < 8; ni++) {
            *(float2*)&Ps[rb    *PS_STR + ni*8 + tg*2] = make_float2(s[ni][0], s[ni][1]);
            *(float2*)&Ps[(rb+8)*PS_STR + ni*8 + tg*2] = make_float2(s[ni][2], s[ni][3]);
        }
        __syncwarp();

        // O += P V
        #pragma unroll
        for (int ks = 0; ks < 8; ks++) {
            int kb8 = ks * 8;
            uint32_t a0 = fbits(Ps[rb    *PS_STR + kb8 + tg    ]);
            uint32_t a1 = fbits(Ps[(rb+8)*PS_STR + kb8 + tg    ]);
            uint32_t a2 = fbits(Ps[rb    *PS_STR + kb8 + tg + 4]);
            uint32_t a3 = fbits(Ps[(rb+8)*PS_STR + kb8 + tg + 4]);
            #pragma unroll
            for (int ni = 0; ni < 8; ni++) {
                uint32_t b0 = fbits(Vs[(kb8 + tg    )*VS_STR + ni*8 + gr]);
                uint32_t b1 = fbits(Vs[(kb8 + tg + 4)*VS_STR + ni*8 + gr]);
                MMA_TF32(oacc[ni], a0, a1, a2, a3, b0, b1);
            }
        }
        __syncthreads();
    }

    // write O to [B,S,D]
    int b_ = bh >> 4, h_ = bh & 15;
    float inv0 = 1.f / lrow[0], inv1 = 1.f / lrow[1];
    int r0g = qt*128 + rb;
    #pragma unroll
    for (int ni = 0; ni < 8; ni++) {
        int cc = h_*64 + ni*8 + tg*2;
        *(float2*)&o[((size_t)b_*SS + r0g    )*DD + cc] = make_float2(oacc[ni][0]*inv0, oacc[ni][1]*inv0);
        *(float2*)&o[((size_t)b_*SS + r0g + 8)*DD + cc] = make_float2(oacc[ni][2]*inv1, oacc[ni][3]*inv1);
    }
}

// ---------------- host launch ------------------------------------------------------
extern "C" void kernel_launch(void* const* d_in, const int* in_sizes, int n_in,
                              void* d_out, int out_size) {
    const float* x   = (const float*)d_in[0];
    const float* Wq  = (const float*)d_in[1];
    const float* bq  = (const float*)d_in[2];
    const float* Wk  = (const float*)d_in[3];
    const float* bk  = (const float*)d_in[4];
    const float* Wv  = (const float*)d_in[5];
    const float* bv  = (const float*)d_in[6];
    const float* Wo  = (const float*)d_in[7];
    const float* bo  = (const float*)d_in[8];
    const float* W1  = (const float*)d_in[9];
    const float* b1  = (const float*)d_in[10];
    const float* W2  = (const float*)d_in[11];
    const float* b2  = (const float*)d_in[12];
    const float* g1  = (const float*)d_in[13];
    const float* be1 = (const float*)d_in[14];
    const float* g2  = (const float*)d_in[15];
    const float* be2 = (const float*)d_in[16];
    float* out = (float*)d_out;

    float *h, *qb, *kb, *vb, *ob, *x1, *h2, *tmid;
    cudaGetSymbolAddress((void**)&h,    g_h);
    cudaGetSymbolAddress((void**)&qb,   g_q);
    cudaGetSymbolAddress((void**)&kb,   g_k);
    cudaGetSymbolAddress((void**)&vb,   g_v);
    cudaGetSymbolAddress((void**)&ob,   g_o);
    cudaGetSymbolAddress((void**)&x1,   g_x1);
    cudaGetSymbolAddress((void**)&h2,   g_h2);
    cudaGetSymbolAddress((void**)&tmid, g_t);

    static bool attr_done = false;
    if (!attr_done) {
        cudaFuncSetAttribute(gemm_tc<0>, cudaFuncAttributeMaxDynamicSharedMemorySize, GEMM_SMEM);
        cudaFuncSetAttribute(gemm_tc<1>, cudaFuncAttributeMaxDynamicSharedMemorySize, GEMM_SMEM);
        cudaFuncSetAttribute(gemm_tc<2>, cudaFuncAttributeMaxDynamicSharedMemorySize, GEMM_SMEM);
        cudaFuncSetAttribute(gemm_tc<3>, cudaFuncAttributeMaxDynamicSharedMemorySize, GEMM_SMEM);
        cudaFuncSetAttribute(attn_tc,    cudaFuncAttributeMaxDynamicSharedMemorySize, ATTN_SMEM);
        attr_done = true;
    }

    dim3 gSq(DD / 128,  MM / 128);    // (8, 64)
    dim3 gFF(DFF / 128, MM / 128);    // (32, 64)

    ln_kernel<<<MM, 256>>>(x, g1, be1, h);

    gemm_tc<0><<<gSq, 256, GEMM_SMEM>>>(h, Wq, bq, nullptr, qb, DD, DD);
    gemm_tc<0><<<gSq, 256, GEMM_SMEM>>>(h, Wk, bk, nullptr, kb, DD, DD);
    gemm_tc<0><<<gSq, 256, GEMM_SMEM>>>(h, Wv, bv, nullptr, vb, DD, DD);

    attn_tc<<<dim3(SS / 128, BB * HH), 256, ATTN_SMEM>>>(qb, kb, vb, ob);

    gemm_tc<1><<<gSq, 256, GEMM_SMEM>>>(ob, Wo, bo, x, x1, DD, DD);

    ln_kernel<<<MM, 256>>>(x1, g2, be2, h2);

    gemm_tc<2><<<gFF, 256, GEMM_SMEM>>>(h2, W1, b1, nullptr, tmid, DD, DFF);
    gemm_tc<3><<<gSq, 256, GEMM_SMEM>>>(tmid, W2, b2, x1, out, DFF, DD);
}